// round 17
// baseline (speedup 1.0000x reference)
#include <cuda_runtime.h>

#define BN 16
#define NC 80
#define GN0 19200
#define GN1 4800
#define GN2 1200
#define NT 25200
#define KMAX 25
#define CAP 3584
#define SCORE_T 0.55f
#define IOU_T 0.5f
#define NEGF (-1e30f)
#define NCELL (BN * NC)
#define NBIN 1024
#define CHUNK 768
#define NGRP (CHUNK / 32)
#define CA 64          // anchors per compact block
#define SCAP 24        // smem staging slots per class per compact block

// Static device scratch (zero-initialized at load; g_cnt re-zeroed by topk each run).
__device__ int    g_cnt[NCELL];
__device__ float  g_cs[(size_t)NCELL * CAP];
__device__ float4 g_cbox[(size_t)NCELL * CAP];
__device__ float  g_kept_score[NCELL * KMAX];
__device__ float4 g_kept_box4[NCELL * KMAX];

__device__ __forceinline__ int bin_of(float s) {
    int b = (int)((s - SCORE_T) * ((float)NBIN / 0.45f));
    return max(0, min(NBIN - 1, b));
}

// Exact reference-order IoU > 0.5 test (canonical corners both sides).
__device__ __forceinline__ bool iou_gt(float cy0, float cx0, float cy1, float cx1,
                                       float py0, float px0, float py1, float px1) {
    float ih = fmaxf(__fsub_rn(fminf(cy1, py1), fmaxf(cy0, py0)), 0.f);
    float iw = fmaxf(__fsub_rn(fminf(cx1, px1), fmaxf(cx0, px0)), 0.f);
    float inter = __fmul_rn(ih, iw);
    float a1 = __fmul_rn(__fsub_rn(py1, py0), __fsub_rn(px1, px0));
    float a2 = __fmul_rn(__fsub_rn(cy1, cy0), __fsub_rn(cx1, cx0));
    float un = __fsub_rn(__fadd_rn(a1, a2), inter);
    return (un > 0.f) && (__fdiv_rn(inter, un) > IOU_T);
}

// Warp argmax of (v, i), lowest-index tiebreak; result broadcast to all lanes.
__device__ __forceinline__ void argmax32(float& v, int& i) {
    #pragma unroll
    for (int o = 16; o; o >>= 1) {
        float ov = __shfl_down_sync(0xffffffffu, v, o);
        int   oi = __shfl_down_sync(0xffffffffu, i, o);
        if (ov > v || (ov == v && oi < i)) { v = ov; i = oi; }
    }
    v = __shfl_sync(0xffffffffu, v, 0);
    i = __shfl_sync(0xffffffffu, i, 0);
}

// ---------------------------------------------------------------------------
// Kernel 1: compact. Block = 64 anchors x 80 classes of one batch.
// conf<=0.55 anchors skipped (predicated loads keep bandwidth savings).
// Loads batched 5-deep for MLP; winners staged in smem, flushed per class.
// ---------------------------------------------------------------------------
__global__ void __launch_bounds__(256) compact_kernel(
        const float* __restrict__ bb0, const float* __restrict__ cf0, const float* __restrict__ cl0,
        const float* __restrict__ bb1, const float* __restrict__ cf1, const float* __restrict__ cl1,
        const float* __restrict__ bb2, const float* __restrict__ cf2, const float* __restrict__ cl2) {
    __shared__ float4 sbox[CA];
    __shared__ float  sconf[CA];
    __shared__ const float4* sclp[CA];
    __shared__ int s_scnt[NC];
    __shared__ float stage_s[NC * SCAP];
    __shared__ unsigned char stage_a[NC * SCAP];

    int b = blockIdx.y;
    int a0 = blockIdx.x * CA;
    int tid = threadIdx.x;

    if (tid < CA) {
        int n = a0 + tid;
        float cfv = -1.f;
        float4 v = make_float4(0.f, 0.f, 0.f, 0.f);
        const float* cp = cl0;
        int loc = 0;
        if (n < NT) {
            const float* bp;
            const float* fp;
            if (n < GN0)            { bp = bb0; fp = cf0; cp = cl0; loc = b * GN0 + n; }
            else if (n < GN0 + GN1) { bp = bb1; fp = cf1; cp = cl1; loc = b * GN1 + (n - GN0); }
            else                    { bp = bb2; fp = cf2; cp = cl2; loc = b * GN2 + (n - GN0 - GN1); }
            v = reinterpret_cast<const float4*>(bp)[loc];
            v.x = fmaxf(v.x, 0.f); v.y = fmaxf(v.y, 0.f);
            v.z = fmaxf(v.z, 0.f); v.w = fmaxf(v.w, 0.f);
            cfv = fp[loc];
        }
        sbox[tid] = v;
        sconf[tid] = cfv;
        sclp[tid] = reinterpret_cast<const float4*>(cp + (size_t)loc * NC);
    }
    if (tid < NC) s_scnt[tid] = 0;
    __syncthreads();

    // phase A: gather per-thread work descriptors (5 quads each)
    int   aa[5], qq[5];
    float cfv[5];
    #pragma unroll
    for (int it = 0; it < 5; it++) {
        int t = it * 256 + tid;          // 0..1279 = 64 anchors * 20 float4s
        aa[it] = t / 20; qq[it] = t % 20;
        cfv[it] = sconf[aa[it]];
    }
    // phase B: 5 independent predicated loads (batched -> MLP ~5)
    float4 cv[5];
    #pragma unroll
    for (int it = 0; it < 5; it++) {
        cv[it] = make_float4(-1.f, -1.f, -1.f, -1.f);
        if (cfv[it] > SCORE_T) cv[it] = __ldg(sclp[aa[it]] + qq[it]);
    }
    // phase C: process
    #pragma unroll
    for (int it = 0; it < 5; it++) {
        if (cfv[it] > SCORE_T) {
            int cb = qq[it] * 4;
            int a = aa[it];
            #pragma unroll
            for (int k = 0; k < 4; k++) {
                float cvk = (k == 0) ? cv[it].x : (k == 1) ? cv[it].y : (k == 2) ? cv[it].z : cv[it].w;
                float s = __fmul_rn(cfv[it], cvk);
                if (s > SCORE_T) {
                    int c = cb + k;
                    int p = atomicAdd(&s_scnt[c], 1);
                    if (p < SCAP) {
                        stage_s[c * SCAP + p] = s;
                        stage_a[c * SCAP + p] = (unsigned char)a;
                    } else {  // rare overflow -> direct global
                        int cell = b * NC + c;
                        int g = atomicAdd(&g_cnt[cell], 1);
                        if (g < CAP) {
                            g_cs[(size_t)cell * CAP + g] = s;
                            g_cbox[(size_t)cell * CAP + g] = sbox[a];
                        }
                    }
                }
            }
        }
    }
    __syncthreads();

    int wid = tid >> 5, lane = tid & 31;
    for (int c = wid; c < NC; c += 8) {
        int cnt = min(s_scnt[c], SCAP);
        if (cnt > 0) {
            int cell = b * NC + c;
            int bas = 0;
            if (lane == 0) bas = atomicAdd(&g_cnt[cell], cnt);
            bas = __shfl_sync(0xffffffffu, bas, 0);
            if (lane < cnt) {
                int idx = bas + lane;
                if (idx < CAP) {
                    g_cs[(size_t)cell * CAP + idx] = stage_s[c * SCAP + lane];
                    g_cbox[(size_t)cell * CAP + idx] = sbox[stage_a[c * SCAP + lane]];
                }
            }
        }
    }
}

// ---------------------------------------------------------------------------
// Kernel 2: NMS via exact descending walk. Block(256) per (b,c) cell.
// ---------------------------------------------------------------------------
__global__ void __launch_bounds__(256) nms_kernel() {
    __shared__ int    hist[NBIN];
    __shared__ float  chs[CHUNK];
    __shared__ float4 cbx[CHUNK];
    __shared__ float  smax[NGRP];
    __shared__ float  ka0[KMAX], ka1[KMAX], ka2[KMAX], ka3[KMAX];  // kept canonical y0,x0,y1,x1
    __shared__ int    s_ctl[4];    // 0:newHi 1:chunk cnt 2:keeps 3:emg flag
    __shared__ int    mask[(CAP + 31) / 32];

    int bc = blockIdx.x;
    int tid = threadIdx.x;
    int M = min(g_cnt[bc], CAP);
    const float*  cs = g_cs   + (size_t)bc * CAP;
    const float4* cb = g_cbox + (size_t)bc * CAP;
    int base = bc * KMAX;

    int hiBin = NBIN;
    int keeps = 0;

    while (keeps < KMAX && hiBin > 0) {
        // ---- pass 1: histogram of unconsumed score range ----
        for (int i = tid; i < NBIN; i += 256) hist[i] = 0;
        for (int i = tid; i < CHUNK; i += 256) chs[i] = NEGF;
        if (tid == 0) s_ctl[1] = 0;
        __syncthreads();
        for (int j = tid; j < M; j += 256) {
            int bi = bin_of(cs[j]);
            if (bi < hiBin) atomicAdd(&hist[bi], 1);
        }
        __syncthreads();
        // ---- threshold scan (thread 0) ----
        if (tid == 0) {
            int lo = hiBin;
            while (lo > 0 && hist[lo - 1] == 0) lo--;
            if (lo == 0)                  { s_ctl[0] = 0;      s_ctl[3] = 0; }
            else if (hist[lo - 1] > CHUNK){ s_ctl[0] = lo - 1; s_ctl[3] = 1; }
            else {
                int acc = 0;
                while (lo > 0) { int h = hist[lo - 1]; if (acc + h > CHUNK) break; acc += h; lo--; }
                s_ctl[0] = lo; s_ctl[3] = 0;
            }
        }
        __syncthreads();
        int newHi = s_ctl[0];
        int emg = s_ctl[3];

        if (!emg) {
            if (newHi < hiBin) {
                // ---- pass 2: compact chunk (bins [newHi, hiBin)) ----
                for (int j = tid; j < M; j += 256) {
                    float s = cs[j];
                    int bi = bin_of(s);
                    if (bi >= newHi && bi < hiBin) {
                        int p = atomicAdd(&s_ctl[1], 1);
                        chs[p] = s;
                        cbx[p] = cb[j];
                    }
                }
                __syncthreads();
                int cnt = s_ctl[1];
                int ng = (cnt + 31) >> 5;
                if (tid < NGRP) {
                    float m = NEGF;
                    #pragma unroll 4
                    for (int t = 0; t < 32; t++) m = fmaxf(m, chs[tid * 32 + t]);
                    smax[tid] = m;
                }
                __syncthreads();
                // ---- warp0 walk ----
                if (tid < 32) {
                    int lane = tid;
                    int kp = keeps;
                    while (kp < KMAX) {
                        float gv = (lane < ng) ? smax[lane] : NEGF;
                        int gi = lane;
                        argmax32(gv, gi);
                        if (gv == NEGF) break;
                        int jj = gi * 32 + lane;
                        float sv = chs[jj];
                        int si = jj;
                        argmax32(sv, si);
                        float4 v = cbx[si];
                        float cy0 = fminf(v.x, v.z), cy1 = fmaxf(v.x, v.z);
                        float cx0 = fminf(v.y, v.w), cx1 = fmaxf(v.y, v.w);
                        bool sup = false;
                        if (lane < kp)
                            sup = iou_gt(cy0, cx0, cy1, cx1, ka0[lane], ka1[lane], ka2[lane], ka3[lane]);
                        unsigned supm = __ballot_sync(0xffffffffu, sup);
                        if (lane == 0) chs[si] = NEGF;
                        __syncwarp();
                        float nv = chs[gi * 32 + lane];
                        #pragma unroll
                        for (int o = 16; o; o >>= 1) nv = fmaxf(nv, __shfl_down_sync(0xffffffffu, nv, o));
                        if (lane == 0) smax[gi] = nv;
                        if (supm == 0) {
                            if (lane == 0) {
                                g_kept_score[base + kp] = sv;
                                g_kept_box4[base + kp] = v;
                                ka0[kp] = cy0; ka1[kp] = cx0; ka2[kp] = cy1; ka3[kp] = cx1;
                            }
                            kp++;
                        }
                        __syncwarp();
                    }
                    if (lane == 0) s_ctl[2] = kp;
                }
                __syncthreads();
                keeps = s_ctl[2];
            }
            hiBin = newHi;
        } else {
            // ---- emergency: single bin larger than CHUNK; serial exact ----
            for (int i = tid; i < (CAP + 31) / 32; i += 256) mask[i] = 0;
            __syncthreads();
            if (tid == 0) {
                int kp = keeps;
                while (kp < KMAX) {
                    float ms = NEGF; int mi = -1;
                    for (int j = 0; j < M; j++) {
                        if ((mask[j >> 5] >> (j & 31)) & 1) continue;
                        float s = cs[j];
                        if (bin_of(s) == newHi && s > ms) { ms = s; mi = j; }
                    }
                    if (mi < 0) break;
                    mask[mi >> 5] |= 1u << (mi & 31);
                    float4 v = cb[mi];
                    float cy0 = fminf(v.x, v.z), cy1 = fmaxf(v.x, v.z);
                    float cx0 = fminf(v.y, v.w), cx1 = fmaxf(v.y, v.w);
                    bool sup = false;
                    for (int q = 0; q < kp && !sup; q++)
                        sup = iou_gt(cy0, cx0, cy1, cx1, ka0[q], ka1[q], ka2[q], ka3[q]);
                    if (!sup) {
                        g_kept_score[base + kp] = ms;
                        g_kept_box4[base + kp] = v;
                        ka0[kp] = cy0; ka1[kp] = cx0; ka2[kp] = cy1; ka3[kp] = cx1;
                        kp++;
                    }
                }
                s_ctl[2] = kp;
            }
            __syncthreads();
            keeps = s_ctl[2];
            hiBin = newHi;
        }
    }
    for (int kk = keeps + tid; kk < KMAX; kk += 256) g_kept_score[base + kk] = NEGF;
}

// ---------------------------------------------------------------------------
// Kernel 3: per-batch top-25 across classes; also zeroes g_cnt for next run.
// Output: boxes[B,25,4] | scores[B,25] | cls[B,25] | valid_det[B]
// ---------------------------------------------------------------------------
__global__ void __launch_bounds__(256) topk_kernel(float* __restrict__ out) {
    __shared__ float  s[NC * KMAX];
    __shared__ float4 sb[NC * KMAX];
    __shared__ float  wr_s[8];
    __shared__ int    wr_i[8];
    __shared__ int    cnt;

    int b = blockIdx.x;
    int tid = threadIdx.x;
    for (int j = tid; j < NC * KMAX; j += 256) {
        s[j]  = g_kept_score[b * NC * KMAX + j];
        sb[j] = g_kept_box4[b * NC * KMAX + j];
    }
    if (tid == 0) cnt = 0;
    if (tid < NC) g_cnt[b * NC + tid] = 0;     // reset for next replay
    __syncthreads();

    for (int k = 0; k < KMAX; k++) {
        float ms = NEGF; int mi = 0x7fffffff;
        for (int j = tid; j < NC * KMAX; j += 256) {
            float v = s[j];
            if (v > ms || (v == ms && j < mi)) { ms = v; mi = j; }
        }
        #pragma unroll
        for (int o = 16; o; o >>= 1) {
            float ov = __shfl_down_sync(0xffffffffu, ms, o);
            int   oi = __shfl_down_sync(0xffffffffu, mi, o);
            if (ov > ms || (ov == ms && oi < mi)) { ms = ov; mi = oi; }
        }
        if ((tid & 31) == 0) { wr_s[tid >> 5] = ms; wr_i[tid >> 5] = mi; }
        __syncthreads();
        if (tid == 0) {
            ms = wr_s[0]; mi = wr_i[0];
            #pragma unroll
            for (int w = 1; w < 8; w++) {
                float ov = wr_s[w]; int oi = wr_i[w];
                if (ov > ms || (ov == ms && oi < mi)) { ms = ov; mi = oi; }
            }
            bool valid = ms > SCORE_T;
            out[BN * KMAX * 4 + b * KMAX + k] = valid ? ms : 0.f;
            out[BN * KMAX * 5 + b * KMAX + k] = valid ? (float)(mi / KMAX) : 0.f;
            float4 v = sb[mi];
            out[(b * KMAX + k) * 4 + 0] = valid ? fminf(fmaxf(v.x, 0.f), 1.f) : 0.f;
            out[(b * KMAX + k) * 4 + 1] = valid ? fminf(fmaxf(v.y, 0.f), 1.f) : 0.f;
            out[(b * KMAX + k) * 4 + 2] = valid ? fminf(fmaxf(v.z, 0.f), 1.f) : 0.f;
            out[(b * KMAX + k) * 4 + 3] = valid ? fminf(fmaxf(v.w, 0.f), 1.f) : 0.f;
            s[mi] = NEGF;
            if (valid) cnt++;
        }
        __syncthreads();
    }
    if (tid == 0) out[BN * KMAX * 6 + b] = (float)cnt;
}

// ---------------------------------------------------------------------------
extern "C" void kernel_launch(void* const* d_in, const int* in_sizes, int n_in,
                              void* d_out, int out_size) {
    const float* bb0 = (const float*)d_in[0];
    const float* cf0 = (const float*)d_in[1];
    const float* cl0 = (const float*)d_in[2];
    const float* bb1 = (const float*)d_in[3];
    const float* cf1 = (const float*)d_in[4];
    const float* cl1 = (const float*)d_in[5];
    const float* bb2 = (const float*)d_in[6];
    const float* cf2 = (const float*)d_in[7];
    const float* cl2 = (const float*)d_in[8];

    dim3 cgrid((NT + CA - 1) / CA, BN);
    compact_kernel<<<cgrid, 256>>>(bb0, cf0, cl0, bb1, cf1, cl1, bb2, cf2, cl2);
    nms_kernel<<<NCELL, 256>>>();
    topk_kernel<<<BN, 256>>>((float*)d_out);
}